// round 4
// baseline (speedup 1.0000x reference)
#include <cuda_runtime.h>
#include <cstdint>

typedef unsigned long long ull;

#define B_ 64
#define S_ 512
#define H_ 1024
#define V_ 128
#define GRID_A 128
#define COLS 8
#define THREADS_A 256
#define KT 256
#define HB (H_ * B_)   /* 65536 floats per time slot, layout [h][b] */

// Hidden-state history, layout (slot, h, b); slot 0 = initial h (transposed),
// slot t+1 = hidden after step t.
__device__ __align__(16) float g_hid[(size_t)(S_ + 1) * HB];
__device__ unsigned int g_cnt;

__device__ __forceinline__ ull dup2(float v) {
    ull r; asm("mov.b64 %0, {%1, %1};" : "=l"(r) : "f"(v)); return r;
}
#define FMA2(d, a, b) asm("fma.rn.f32x2 %0, %1, %2, %0;" : "+l"(d) : "l"(a), "l"(b))
__device__ __forceinline__ float lo2(ull v) { return __uint_as_float((unsigned)v); }
__device__ __forceinline__ float hi2(ull v) { return __uint_as_float((unsigned)(v >> 32)); }

// ---------------------------------------------------------------------------
// Init: reset barrier counter, transpose initial h (B,H) -> g_hid slot 0 [h][b]
// ---------------------------------------------------------------------------
__global__ void rnn_init(const float* __restrict__ h0) {
    int i = blockIdx.x * blockDim.x + threadIdx.x;
    if (i == 0) g_cnt = 0u;
    if (i < HB) {
        int b = i >> 10;        // i = b*1024 + h
        int hh = i & 1023;
        g_hid[(size_t)hh * B_ + b] = h0[i];
    }
}

// ---------------------------------------------------------------------------
// cp.async staging of one k-tile of h (KT rows x 64 batches = 64 KB)
// ---------------------------------------------------------------------------
__device__ __forceinline__ void stage_tile(uint32_t dst_s, const float* src, int tid) {
#pragma unroll
    for (int j = 0; j < 16; ++j) {
        int c = tid + j * THREADS_A;               // 0..4095 16B chunks
        asm volatile("cp.async.cg.shared.global [%0], [%1], 16;\n"
                     :: "r"(dst_s + (uint32_t)c * 16u), "l"(src + (size_t)c * 4)
                     : "memory");
    }
}

// ---------------------------------------------------------------------------
// Persistent recurrence kernel. 128 CTAs x 256 threads, each CTA owns 8 cols.
// Identical structure to the proven R1 kernel; only the inner product is
// rewritten with packed fma.rn.f32x2 over batch pairs (W duplicated in smem).
// ---------------------------------------------------------------------------
__global__ __launch_bounds__(THREADS_A, 1) void rnn_recur(
    const int* __restrict__ x, const float* __restrict__ W_xh,
    const float* __restrict__ W_hh, const float* __restrict__ b_h,
    float* __restrict__ hfinal_out)
{
    extern __shared__ float sm[];
    float* h_sm   = sm;                              // 2 * KT * 64 floats (double buffer)
    ull*   w_smd  = (ull*)(sm + 2 * KT * B_);        // 8 * 1024 dup(w,w)   64KB
    float* wxh_sm = (float*)(w_smd + COLS * 1024);   // 128 * 8
    float* red_sm = wxh_sm + V_ * COLS;              // 256 * 8
    float* bh_sm  = red_sm + THREADS_A * 8;          // 8
    int*   x_sm   = (int*)(bh_sm + COLS);            // 64

    const int tid   = threadIdx.x;
    const int cbase = blockIdx.x * COLS;

    // One-time preload: W_hh slice duplicated as (w,w) pairs, layout [c][k]
    for (int i = tid; i < H_ * COLS; i += THREADS_A) {
        int c = i >> 10, k = i & 1023;
        w_smd[i] = dup2(W_hh[(size_t)k * H_ + cbase + c]);
    }
    for (int i = tid; i < V_ * COLS; i += THREADS_A) {
        int v = i >> 3, c = i & 7;
        wxh_sm[i] = W_xh[(size_t)v * H_ + cbase + c];
    }
    if (tid < COLS) bh_sm[tid] = b_h[cbase + tid];
    __syncthreads();

    const int g  = tid & 63;        // (batch-quad, col-pair) group
    const int kg = tid >> 6;        // k-split group 0..3
    const int b0 = (g & 15) << 2;   // 4 consecutive batches
    const int c0 = (g >> 4) << 1;   // 2 consecutive local cols

    uint32_t hs_base = (uint32_t)__cvta_generic_to_shared(h_sm);

    for (int t = 0; t < S_; ++t) {
        const float* hprev = g_hid + (size_t)t * HB;
        if (tid < B_) x_sm[tid] = x[tid * S_ + t];

        ull a00 = 0, a01 = 0, a10 = 0, a11 = 0;   // [col][batch-pair]

        stage_tile(hs_base, hprev, tid);
        asm volatile("cp.async.commit_group;\n" ::: "memory");

        for (int tile = 0; tile < 4; ++tile) {
            if (tile < 3) {
                stage_tile(hs_base + (uint32_t)(((tile + 1) & 1) * KT * B_ * 4),
                           hprev + (size_t)(tile + 1) * KT * B_, tid);
                asm volatile("cp.async.commit_group;\n" ::: "memory");
                asm volatile("cp.async.wait_group 1;\n" ::: "memory");
            } else {
                asm volatile("cp.async.wait_group 0;\n" ::: "memory");
            }
            __syncthreads();

            const float* hb = h_sm + (tile & 1) * KT * B_;
            const ull* wA = w_smd + c0 * 1024 + tile * KT + kg * 64;
            const ull* wB = wA + 1024;
            const float* hp = hb + (kg * 64) * B_ + b0;
#pragma unroll
            for (int j = 0; j < 64; j += 4) {
                ulonglong2 waA = *(const ulonglong2*)(wA + j);      // k j, j+1
                ulonglong2 waB = *(const ulonglong2*)(wA + j + 2);  // k j+2, j+3
                ulonglong2 wbA = *(const ulonglong2*)(wB + j);
                ulonglong2 wbB = *(const ulonglong2*)(wB + j + 2);
                ulonglong2 h0 = *(const ulonglong2*)(hp + (j + 0) * B_);
                ulonglong2 h1 = *(const ulonglong2*)(hp + (j + 1) * B_);
                ulonglong2 h2 = *(const ulonglong2*)(hp + (j + 2) * B_);
                ulonglong2 h3 = *(const ulonglong2*)(hp + (j + 3) * B_);
                FMA2(a00, h0.x, waA.x); FMA2(a01, h0.y, waA.x);
                FMA2(a10, h0.x, wbA.x); FMA2(a11, h0.y, wbA.x);
                FMA2(a00, h1.x, waA.y); FMA2(a01, h1.y, waA.y);
                FMA2(a10, h1.x, wbA.y); FMA2(a11, h1.y, wbA.y);
                FMA2(a00, h2.x, waB.x); FMA2(a01, h2.y, waB.x);
                FMA2(a10, h2.x, wbB.x); FMA2(a11, h2.y, wbB.x);
                FMA2(a00, h3.x, waB.y); FMA2(a01, h3.y, waB.y);
                FMA2(a10, h3.x, wbB.y); FMA2(a11, h3.y, wbB.y);
            }
            __syncthreads();
        }

        // Unpack packed accumulators into R1's scalar layout, then identical tail.
        float acc[8];
        acc[0] = lo2(a00); acc[1] = hi2(a00); acc[2] = lo2(a01); acc[3] = hi2(a01);
        acc[4] = lo2(a10); acc[5] = hi2(a10); acc[6] = lo2(a11); acc[7] = hi2(a11);

        *(float4*)(red_sm + tid * 8)     = make_float4(acc[0], acc[1], acc[2], acc[3]);
        *(float4*)(red_sm + tid * 8 + 4) = make_float4(acc[4], acc[5], acc[6], acc[7]);
        __syncthreads();

        if (tid < 64) {
            float s[8];
#pragma unroll
            for (int i = 0; i < 8; ++i)
                s[i] = red_sm[g * 8 + i] + red_sm[(g + 64) * 8 + i] +
                       red_sm[(g + 128) * 8 + i] + red_sm[(g + 192) * 8 + i];

            float o0[4], o1[4];
#pragma unroll
            for (int bb = 0; bb < 4; ++bb) {
                int xv = x_sm[b0 + bb];
                o0[bb] = tanhf(s[bb]     + wxh_sm[xv * 8 + c0]     + bh_sm[c0]);
                o1[bb] = tanhf(s[4 + bb] + wxh_sm[xv * 8 + c0 + 1] + bh_sm[c0 + 1]);
            }
            float* dst = g_hid + (size_t)(t + 1) * HB + (size_t)(cbase + c0) * B_ + b0;
            *(float4*)(dst)      = make_float4(o0[0], o0[1], o0[2], o0[3]);
            *(float4*)(dst + B_) = make_float4(o1[0], o1[1], o1[2], o1[3]);
            if (t == S_ - 1) {
#pragma unroll
                for (int bb = 0; bb < 4; ++bb) {
                    hfinal_out[(size_t)(b0 + bb) * H_ + cbase + c0]     = o0[bb];
                    hfinal_out[(size_t)(b0 + bb) * H_ + cbase + c0 + 1] = o1[bb];
                }
            }
        }

        // Grid barrier: release(fence)+count, acquire(spin+fence)
        __threadfence();
        __syncthreads();
        if (tid == 0) {
            unsigned target = (unsigned)(t + 1) * (unsigned)GRID_A;
            atomicAdd(&g_cnt, 1u);
            volatile unsigned* vc = &g_cnt;
            while ((int)(*vc - target) < 0) { }
            __threadfence();
        }
        __syncthreads();
    }
}

// ---------------------------------------------------------------------------
// logits = hidden @ W_out + b_out.  M=32768 (m = t*64+b), N=128, K=1024.
// A read from g_hid (t+1, k, b). 256 CTAs, 128x128 tile, 8x8 micro. (R1-proven)
// ---------------------------------------------------------------------------
__global__ __launch_bounds__(256) void rnn_logits(
    const float* __restrict__ W_out, const float* __restrict__ b_out,
    float* __restrict__ out)
{
    __shared__ float a_sm[32][128];
    __shared__ float b_sm[32][128];
    const int tid = threadIdx.x;
    const int M0  = blockIdx.x * 128;
    const int t0  = M0 >> 6;
    const int tx  = tid & 15, ty = tid >> 4;

    float acc[8][8];
#pragma unroll
    for (int i = 0; i < 8; ++i)
#pragma unroll
        for (int j = 0; j < 8; ++j) acc[i][j] = 0.f;

    for (int kt = 0; kt < 32; ++kt) {
        int k0 = kt * 32;
#pragma unroll
        for (int j2 = 0; j2 < 4; ++j2) {
            int q = tid + j2 * 256;
            int k = q >> 5;
            int m = (q & 31) << 2;
            const float* asrc = g_hid + (size_t)(t0 + (m >> 6) + 1) * HB +
                                (size_t)(k0 + k) * B_ + (m & 63);
            *(float4*)&a_sm[k][m] = *(const float4*)asrc;
            *(float4*)&b_sm[k][m] = *(const float4*)&W_out[(size_t)(k0 + k) * V_ + m];
        }
        __syncthreads();
#pragma unroll
        for (int k = 0; k < 32; ++k) {
            float4 a0 = *(float4*)&a_sm[k][ty * 8];
            float4 a1 = *(float4*)&a_sm[k][ty * 8 + 4];
            float4 w0 = *(float4*)&b_sm[k][tx * 8];
            float4 w1 = *(float4*)&b_sm[k][tx * 8 + 4];
            float av[8] = {a0.x, a0.y, a0.z, a0.w, a1.x, a1.y, a1.z, a1.w};
            float bv[8] = {w0.x, w0.y, w0.z, w0.w, w1.x, w1.y, w1.z, w1.w};
#pragma unroll
            for (int i = 0; i < 8; ++i)
#pragma unroll
                for (int j = 0; j < 8; ++j) acc[i][j] += av[i] * bv[j];
        }
        __syncthreads();
    }

    float bo[8];
#pragma unroll
    for (int j = 0; j < 8; ++j) bo[j] = b_out[tx * 8 + j];
#pragma unroll
    for (int i = 0; i < 8; ++i) {
        int mg = M0 + ty * 8 + i;
        int tt = mg >> 6, b = mg & 63;
        float* op = out + ((size_t)b * S_ + tt) * V_ + tx * 8;
        *(float4*)op       = make_float4(acc[i][0] + bo[0], acc[i][1] + bo[1],
                                         acc[i][2] + bo[2], acc[i][3] + bo[3]);
        *(float4*)(op + 4) = make_float4(acc[i][4] + bo[4], acc[i][5] + bo[5],
                                         acc[i][6] + bo[6], acc[i][7] + bo[7]);
    }
}

// ---------------------------------------------------------------------------
extern "C" void kernel_launch(void* const* d_in, const int* in_sizes, int n_in,
                              void* d_out, int out_size) {
    (void)in_sizes; (void)n_in; (void)out_size;
    const int*   x     = (const int*)  d_in[0];
    const float* h0    = (const float*)d_in[1];
    const float* W_xh  = (const float*)d_in[2];
    const float* W_hh  = (const float*)d_in[3];
    const float* b_h   = (const float*)d_in[4];
    const float* W_out = (const float*)d_in[5];
    const float* b_out = (const float*)d_in[6];
    float* out = (float*)d_out;

    const int SMEM_A = (2 * KT * B_) * (int)sizeof(float) +
                       (COLS * 1024) * (int)sizeof(ull) +
                       (V_ * COLS + THREADS_A * 8 + COLS) * (int)sizeof(float) +
                       B_ * (int)sizeof(int);
    cudaFuncSetAttribute(rnn_recur, cudaFuncAttributeMaxDynamicSharedMemorySize, SMEM_A);

    rnn_init<<<(HB + 255) / 256, 256>>>(h0);
    rnn_recur<<<GRID_A, THREADS_A, SMEM_A>>>(x, W_xh, W_hh, b_h,
                                             out + (size_t)B_ * S_ * V_);
    rnn_logits<<<(B_ * S_) / 128, 256>>>(W_out, b_out, out);
}

// round 6
// speedup vs baseline: 1.2211x; 1.2211x over previous
#include <cuda_runtime.h>
#include <cstdint>

#define B_ 64
#define S_ 512
#define H_ 1024
#define V_ 128
#define THREADS_A 256
#define HB (H_ * B_)   /* 65536 floats per time slot, layout [h][b] */
#define WPAD 1036      /* w_sm column stride (floats), 16B-aligned, 2-way conflict */

// Hidden-state history, layout (slot, h, b); slot 0 = initial h (transposed),
// slot t+1 = hidden after step t.
__device__ __align__(16) float g_hid[(size_t)(S_ + 1) * HB];
// One full-barrier counter per batch-group (4 pools of 32 CTAs), 128B apart.
__device__ unsigned int g_cntb[4 * 32];

// ---------------------------------------------------------------------------
// Init: reset counters, transpose initial h (B,H) -> g_hid slot 0 [h][b]
// ---------------------------------------------------------------------------
__global__ void rnn_init(const float* __restrict__ h0) {
    int i = blockIdx.x * blockDim.x + threadIdx.x;
    if (i < 4 * 32) g_cntb[i] = 0u;
    if (i < HB) {
        int b = i >> 10;        // i = b*1024 + h
        int hh = i & 1023;
        g_hid[(size_t)hh * B_ + b] = h0[i];
    }
}

// ---------------------------------------------------------------------------
// cp.async staging of one k-tile of h: 512 k-rows x 16 batches = 32 KB.
// src_base = g_hid + t*HB + tile*512*64 + boff (16-batch slice, row stride 64).
// ---------------------------------------------------------------------------
__device__ __forceinline__ void stage_tile(uint32_t dst_s, const float* src_base, int tid) {
#pragma unroll
    for (int j = 0; j < 8; ++j) {
        int c = tid + j * THREADS_A;               // 0..2047 16B chunks
        int row = c >> 2, q = c & 3;
        asm volatile("cp.async.cg.shared.global [%0], [%1], 16;\n"
                     :: "r"(dst_s + (uint32_t)c * 16u),
                        "l"(src_base + (size_t)row * B_ + q * 4)
                     : "memory");
    }
}

// ---------------------------------------------------------------------------
// Persistent recurrence. 128 CTAs x 256 threads. CTA (bg, cg) owns
// batches [16bg, 16bg+16) x cols [32cg, 32cg+32). Four decoupled pools of 32
// CTAs (per bg), each using R1's proven full-barrier idiom.
// ---------------------------------------------------------------------------
__global__ __launch_bounds__(THREADS_A, 1) void rnn_recur(
    const int* __restrict__ x, const float* __restrict__ W_xh,
    const float* __restrict__ W_hh, const float* __restrict__ b_h,
    float* __restrict__ hfinal_out)
{
    extern __shared__ float sm[];
    float* h_sm   = sm;                              // 2 * 512 * 16 (double buffer) 64KB
    float* w_sm   = h_sm + 2 * 512 * 16;             // 32 * WPAD                  ~130KB
    float* wxh_sm = w_sm + 32 * WPAD;                // 128 * 32                    16KB
    float* red_sm = wxh_sm + V_ * 32;                // 256 * 8                      8KB
    float* bh_sm  = red_sm + THREADS_A * 8;          // 32
    int*   x_sm   = (int*)(bh_sm + 32);              // 16

    const int tid   = threadIdx.x;
    const int bg    = blockIdx.x >> 5;               // batch group 0..3
    const int cg    = blockIdx.x & 31;               // col group   0..31
    const int cbase = cg * 32;
    const int boff  = bg * 16;

    // One-time preload: W_hh col slice (32 cols), W_xh slice, bias.
    for (int i = tid; i < H_ * 32; i += THREADS_A) {
        int k = i >> 5, c = i & 31;
        w_sm[c * WPAD + k] = W_hh[(size_t)k * H_ + cbase + c];
    }
    for (int i = tid; i < V_ * 32; i += THREADS_A) {
        int v = i >> 5, c = i & 31;
        wxh_sm[i] = W_xh[(size_t)v * H_ + cbase + c];
    }
    if (tid < 32) bh_sm[tid] = b_h[cbase + tid];
    __syncthreads();

    const int g  = tid & 63;        // 64 groups = 4 batch-quads x 16 col-pairs
    const int kg = tid >> 6;        // k-split group 0..3 (128 k each per tile)
    const int b0 = (g & 3) * 4;     // 4 consecutive local batches
    const int c0 = (g >> 2) * 2;    // 2 consecutive local cols

    const float* wp0 = w_sm + c0 * WPAD;
    const float* wp1 = wp0 + WPAD;
    uint32_t hs_base = (uint32_t)__cvta_generic_to_shared(h_sm);

    for (int t = 0; t < S_; ++t) {
        const float* hsrc = g_hid + (size_t)t * HB + boff;
        if (tid < 16) x_sm[tid] = x[(size_t)(boff + tid) * S_ + t];

        float acc[8];
#pragma unroll
        for (int i = 0; i < 8; ++i) acc[i] = 0.f;

        stage_tile(hs_base, hsrc, tid);
        asm volatile("cp.async.commit_group;\n" ::: "memory");

#pragma unroll
        for (int tile = 0; tile < 2; ++tile) {
            if (tile == 0) {
                stage_tile(hs_base + (uint32_t)(512 * 16 * 4),
                           hsrc + (size_t)512 * B_, tid);
                asm volatile("cp.async.commit_group;\n" ::: "memory");
                asm volatile("cp.async.wait_group 1;\n" ::: "memory");
            } else {
                asm volatile("cp.async.wait_group 0;\n" ::: "memory");
            }
            __syncthreads();

            const float* hp = h_sm + tile * (512 * 16) + (kg * 128) * 16 + b0;
            const float* wa = wp0 + tile * 512 + kg * 128;
            const float* wb = wp1 + tile * 512 + kg * 128;
#pragma unroll
            for (int j = 0; j < 128; j += 4) {
                float4 wa4 = *(const float4*)(wa + j);
                float4 wb4 = *(const float4*)(wb + j);
#pragma unroll
                for (int jj = 0; jj < 4; ++jj) {
                    float4 hv = *(const float4*)(hp + (j + jj) * 16);
                    float wax = (&wa4.x)[jj];
                    float wbx = (&wb4.x)[jj];
                    acc[0] += hv.x * wax; acc[1] += hv.y * wax;
                    acc[2] += hv.z * wax; acc[3] += hv.w * wax;
                    acc[4] += hv.x * wbx; acc[5] += hv.y * wbx;
                    acc[6] += hv.z * wbx; acc[7] += hv.w * wbx;
                }
            }
            if (tile == 0) __syncthreads();   // before next wait/compute phase
        }

        // Reduce k-split partials
        *(float4*)(red_sm + tid * 8)     = make_float4(acc[0], acc[1], acc[2], acc[3]);
        *(float4*)(red_sm + tid * 8 + 4) = make_float4(acc[4], acc[5], acc[6], acc[7]);
        __syncthreads();

        if (tid < 64) {
            float s[8];
#pragma unroll
            for (int i = 0; i < 8; ++i)
                s[i] = red_sm[g * 8 + i] + red_sm[(g + 64) * 8 + i] +
                       red_sm[(g + 128) * 8 + i] + red_sm[(g + 192) * 8 + i];

            float o0[4], o1[4];
#pragma unroll
            for (int bb = 0; bb < 4; ++bb) {
                int xv = x_sm[b0 + bb];
                o0[bb] = tanhf(s[bb]     + wxh_sm[xv * 32 + c0]     + bh_sm[c0]);
                o1[bb] = tanhf(s[4 + bb] + wxh_sm[xv * 32 + c0 + 1] + bh_sm[c0 + 1]);
            }
            float* dst = g_hid + (size_t)(t + 1) * HB +
                         (size_t)(cbase + c0) * B_ + boff + b0;
            *(float4*)(dst)      = make_float4(o0[0], o0[1], o0[2], o0[3]);
            *(float4*)(dst + B_) = make_float4(o1[0], o1[1], o1[2], o1[3]);
            if (t == S_ - 1) {
#pragma unroll
                for (int bb = 0; bb < 4; ++bb) {
                    hfinal_out[(size_t)(boff + b0 + bb) * H_ + cbase + c0]     = o0[bb];
                    hfinal_out[(size_t)(boff + b0 + bb) * H_ + cbase + c0 + 1] = o1[bb];
                }
            }
        }

        // R1-proven full barrier, among this batch-group's 32 CTAs only.
        __threadfence();
        __syncthreads();
        if (tid == 0) {
            unsigned target = (unsigned)(t + 1) * 32u;
            atomicAdd(&g_cntb[bg * 32], 1u);
            volatile unsigned* vc = &g_cntb[bg * 32];
            while ((int)(*vc - target) < 0) { }
            __threadfence();
        }
        __syncthreads();
    }
}

// ---------------------------------------------------------------------------
// logits = hidden @ W_out + b_out.  M=32768 (m = t*64+b), N=128, K=1024.
// A read from g_hid (t+1, k, b). 256 CTAs, 128x128 tile, 8x8 micro. (proven)
// ---------------------------------------------------------------------------
__global__ __launch_bounds__(256) void rnn_logits(
    const float* __restrict__ W_out, const float* __restrict__ b_out,
    float* __restrict__ out)
{
    __shared__ float a_sm[32][128];
    __shared__ float b_sm[32][128];
    const int tid = threadIdx.x;
    const int M0  = blockIdx.x * 128;
    const int t0  = M0 >> 6;
    const int tx  = tid & 15, ty = tid >> 4;

    float acc[8][8];
#pragma unroll
    for (int i = 0; i < 8; ++i)
#pragma unroll
        for (int j = 0; j < 8; ++j) acc[i][j] = 0.f;

    for (int kt = 0; kt < 32; ++kt) {
        int k0 = kt * 32;
#pragma unroll
        for (int j2 = 0; j2 < 4; ++j2) {
            int q = tid + j2 * 256;
            int k = q >> 5;
            int m = (q & 31) << 2;
            const float* asrc = g_hid + (size_t)(t0 + (m >> 6) + 1) * HB +
                                (size_t)(k0 + k) * B_ + (m & 63);
            *(float4*)&a_sm[k][m] = *(const float4*)asrc;
            *(float4*)&b_sm[k][m] = *(const float4*)&W_out[(size_t)(k0 + k) * V_ + m];
        }
        __syncthreads();
#pragma unroll
        for (int k = 0; k < 32; ++k) {
            float4 a0 = *(float4*)&a_sm[k][ty * 8];
            float4 a1 = *(float4*)&a_sm[k][ty * 8 + 4];
            float4 w0 = *(float4*)&b_sm[k][tx * 8];
            float4 w1 = *(float4*)&b_sm[k][tx * 8 + 4];
            float av[8] = {a0.x, a0.y, a0.z, a0.w, a1.x, a1.y, a1.z, a1.w};
            float bv[8] = {w0.x, w0.y, w0.z, w0.w, w1.x, w1.y, w1.z, w1.w};
#pragma unroll
            for (int i = 0; i < 8; ++i)
#pragma unroll
                for (int j = 0; j < 8; ++j) acc[i][j] += av[i] * bv[j];
        }
        __syncthreads();
    }

    float bo[8];
#pragma unroll
    for (int j = 0; j < 8; ++j) bo[j] = b_out[tx * 8 + j];
#pragma unroll
    for (int i = 0; i < 8; ++i) {
        int mg = M0 + ty * 8 + i;
        int tt = mg >> 6, b = mg & 63;
        float* op = out + ((size_t)b * S_ + tt) * V_ + tx * 8;
        *(float4*)op       = make_float4(acc[i][0] + bo[0], acc[i][1] + bo[1],
                                         acc[i][2] + bo[2], acc[i][3] + bo[3]);
        *(float4*)(op + 4) = make_float4(acc[i][4] + bo[4], acc[i][5] + bo[5],
                                         acc[i][6] + bo[6], acc[i][7] + bo[7]);
    }
}

// ---------------------------------------------------------------------------
extern "C" void kernel_launch(void* const* d_in, const int* in_sizes, int n_in,
                              void* d_out, int out_size) {
    (void)in_sizes; (void)n_in; (void)out_size;
    const int*   x     = (const int*)  d_in[0];
    const float* h0    = (const float*)d_in[1];
    const float* W_xh  = (const float*)d_in[2];
    const float* W_hh  = (const float*)d_in[3];
    const float* b_h   = (const float*)d_in[4];
    const float* W_out = (const float*)d_in[5];
    const float* b_out = (const float*)d_in[6];
    float* out = (float*)d_out;

    const int SMEM_A = (2 * 512 * 16 + 32 * WPAD + V_ * 32 + THREADS_A * 8 + 32)
                           * (int)sizeof(float) + 16 * (int)sizeof(int);
    cudaFuncSetAttribute(rnn_recur, cudaFuncAttributeMaxDynamicSharedMemorySize, SMEM_A);

    rnn_init<<<(HB + 255) / 256, 256>>>(h0);
    rnn_recur<<<128, THREADS_A, SMEM_A>>>(x, W_xh, W_hh, b_h,
                                          out + (size_t)B_ * S_ * V_);
    rnn_logits<<<(B_ * S_) / 128, 256>>>(W_out, b_out, out);
}